// round 16
// baseline (speedup 1.0000x reference)
#include <cuda_runtime.h>
#include <cuda_fp16.h>
#include <mma.h>
#include <cstdint>

using namespace nvcuda;

#define H        256
#define FOURH    1024
#define NG       2048
#define APG      64
#define GRIDA    444          // attention: 3 CTAs per SM
#define TILE_F   (APG*H)
#define TILE_B   (TILE_F*4)   // fp32 tile bytes
#define TILE_HB  (TILE_F*2)   // fp16 tile bytes

// ---------------- device scratch ----------------
__device__ __align__(128) __half g_Wc16[FOURH * H];      // fp16 folded weights
__device__ float   g_bc[FOURH];
__device__ float   g_q0[H];
__device__ float   g_c0[H];
__device__ float   g_c [NG * H];
__device__ __align__(128) __half g_h16[NG * H];          // fp16 h (= r)
__device__ float   g_gates[NG * FOURH];
__device__ __align__(128) __half2 g_xh2[(size_t)NG * 8192];  // fp16 copy of x

__device__ __forceinline__ float sigmoidf_(float v) {
    return 1.0f / (1.0f + __expf(-v));
}

// ---------------- prep ----------------
__global__ void prep_kernel(const float* __restrict__ W_ih,
                            const float* __restrict__ W_hh,
                            const float* __restrict__ b_ih,
                            const float* __restrict__ b_hh) {
    int idx = blockIdx.x * 256 + threadIdx.x;
    if (idx < FOURH * H)
        g_Wc16[idx] = __float2half(W_ih[idx] + W_hh[idx]);
    if (idx < FOURH) g_bc[idx] = b_ih[idx] + b_hh[idx];
    if (idx < H) {
        float gi = b_ih[idx]       + b_hh[idx];
        float gg = b_ih[512 + idx] + b_hh[512 + idx];
        float go = b_ih[768 + idx] + b_hh[768 + idx];
        float c  = sigmoidf_(gi) * tanhf(gg);
        g_c0[idx] = c;
        g_q0[idx] = sigmoidf_(go) * tanhf(c);
    }
}

// ---------------- GEMM: gates = h16 @ Wc16^T via wmma (fp32 accum) ----------------
#define GW_SMEM (2 * 128 * 256 * 2)

__global__ void __launch_bounds__(256) gemm_wmma_kernel() {
    extern __shared__ __align__(16) __half smh[];
    __half* As = smh;                  // [128][256]
    __half* Bs = smh + 128 * 256;      // [128][256]

    int tid = threadIdx.x;
    int mb  = blockIdx.y * 128;
    int nb  = blockIdx.x * 128;

    {
        const uint4* srcA = (const uint4*)(g_h16  + (size_t)mb * H);
        const uint4* srcB = (const uint4*)(g_Wc16 + (size_t)nb * H);
        uint4* dA = (uint4*)As;
        uint4* dB = (uint4*)Bs;
        #pragma unroll
        for (int i = 0; i < 16; ++i) dA[tid + i * 256] = srcA[tid + i * 256];
        #pragma unroll
        for (int i = 0; i < 16; ++i) dB[tid + i * 256] = srcB[tid + i * 256];
    }
    __syncthreads();

    int w  = tid >> 5;
    int wm = (w >> 1) * 32;
    int wn = (w & 1) * 64;

    wmma::fragment<wmma::accumulator, 16, 16, 16, float> acc[2][4];
    #pragma unroll
    for (int i = 0; i < 2; ++i)
        #pragma unroll
        for (int j = 0; j < 4; ++j) wmma::fill_fragment(acc[i][j], 0.0f);

    #pragma unroll
    for (int k = 0; k < H; k += 16) {
        wmma::fragment<wmma::matrix_a, 16, 16, 16, __half, wmma::row_major> af[2];
        wmma::fragment<wmma::matrix_b, 16, 16, 16, __half, wmma::col_major> bf[4];
        #pragma unroll
        for (int i = 0; i < 2; ++i)
            wmma::load_matrix_sync(af[i], As + (wm + 16 * i) * H + k, H);
        #pragma unroll
        for (int j = 0; j < 4; ++j)
            wmma::load_matrix_sync(bf[j], Bs + (wn + 16 * j) * H + k, H);
        #pragma unroll
        for (int i = 0; i < 2; ++i)
            #pragma unroll
            for (int j = 0; j < 4; ++j)
                wmma::mma_sync(acc[i][j], af[i], bf[j], acc[i][j]);
    }

    #pragma unroll
    for (int i = 0; i < 2; ++i)
        #pragma unroll
        for (int j = 0; j < 4; ++j)
            wmma::store_matrix_sync(
                &g_gates[(size_t)(mb + wm + 16 * i) * FOURH + nb + wn + 16 * j],
                acc[i][j], FOURH, wmma::mem_row_major);
}

// ---------------- pass 0: fp32 attention (q = q0) + fp16 tile export ----------------
#define A32_FLOATS (TILE_F + H + APG + 1024)
#define A32_SMEM   (A32_FLOATS*4 + 8)

__global__ void __launch_bounds__(512, 3) attn0_kernel(const float* __restrict__ x) {
    extern __shared__ __align__(16) unsigned char smraw[];
    float* xs  = (float*)smraw;              // [64][256] fp32
    float* qs  = xs + TILE_F;                // [256]
    float* sc  = qs + H;                     // [64]
    float* red = sc + APG;                   // [512] float2
    uint32_t smem_base;
    asm("{ .reg .u64 t; cvta.to.shared.u64 t, %1; cvt.u32.u64 %0, t; }"
        : "=r"(smem_base) : "l"(smraw));
    uint32_t mbar = smem_base + A32_FLOATS * 4;

    int tid  = threadIdx.x;
    int lane = tid & 31;
    int w    = tid >> 5;

    if (tid == 0)
        asm volatile("mbarrier.init.shared.b64 [%0], 1;" :: "r"(mbar) : "memory");
    __syncthreads();

    int ph = 0;
    for (int b = blockIdx.x; b < NG; b += GRIDA) {
        if (tid == 0) {
            asm volatile("mbarrier.arrive.expect_tx.shared.b64 _, [%0], %1;"
                         :: "r"(mbar), "r"(TILE_B) : "memory");
            asm volatile("cp.async.bulk.shared::cta.global.mbarrier::complete_tx::bytes "
                         "[%0], [%1], %2, [%3];"
                         :: "r"(smem_base), "l"(x + (size_t)b * TILE_F),
                            "r"(TILE_B), "r"(mbar) : "memory");
        }
        if (tid < H) qs[tid] = g_q0[tid];

        {
            uint32_t done;
            do {
                asm volatile(
                    "{ .reg .pred p; "
                    "mbarrier.try_wait.parity.acquire.cta.shared::cta.b64 p, [%1], %2, 0x989680; "
                    "selp.b32 %0, 1, 0, p; }"
                    : "=r"(done) : "r"(mbar), "r"(ph) : "memory");
            } while (!done);
            ph ^= 1;
        }
        __syncthreads();

        // export tile as fp16 (uint2 stores, proven in R13)
        {
            const float4* src4 = (const float4*)xs;
            uint2* dst2 = (uint2*)(g_xh2 + (size_t)b * 8192);
            #pragma unroll
            for (int it = 0; it < 8; ++it) {
                int idx = tid + it * 512;
                float4 v = src4[idx];
                __half2 h0 = __floats2half2_rn(v.x, v.y);
                __half2 h1 = __floats2half2_rn(v.z, v.w);
                uint2 u;
                u.x = *(uint32_t*)&h0;
                u.y = *(uint32_t*)&h1;
                dst2[idx] = u;
            }
        }

        // scores: 16 warps x 4 atoms; float4 loads
        float4 q4a = *(const float4*)&qs[4 * lane];
        float4 q4b = *(const float4*)&qs[128 + 4 * lane];
        #pragma unroll
        for (int aa = 0; aa < 4; ++aa) {
            int a = w * 4 + aa;
            const float* xr = xs + a * H;
            float4 xa = *(const float4*)&xr[4 * lane];
            float4 xb = *(const float4*)&xr[128 + 4 * lane];
            float p = xa.x*q4a.x + xa.y*q4a.y + xa.z*q4a.z + xa.w*q4a.w
                    + xb.x*q4b.x + xb.y*q4b.y + xb.z*q4b.z + xb.w*q4b.w;
            #pragma unroll
            for (int off = 16; off; off >>= 1)
                p += __shfl_xor_sync(0xffffffffu, p, off);
            if (lane == 0) sc[a] = p;
        }
        __syncthreads();

        // softmax over 64 (warp 0)
        if (w == 0) {
            float v0 = sc[lane], v1 = sc[lane + 32];
            float mx = fmaxf(v0, v1);
            #pragma unroll
            for (int off = 16; off; off >>= 1)
                mx = fmaxf(mx, __shfl_xor_sync(0xffffffffu, mx, off));
            float e0 = __expf(v0 - mx), e1 = __expf(v1 - mx);
            float s = e0 + e1;
            #pragma unroll
            for (int off = 16; off; off >>= 1)
                s += __shfl_xor_sync(0xffffffffu, s, off);
            float inv = 1.0f / s;
            sc[lane]      = e0 * inv;
            sc[lane + 32] = e1 * inv;
        }
        __syncthreads();

        // weighted sum: thread -> feature pair, quarter of atoms (float2 loads)
        {
            int fp = tid & 127;
            int qt = tid >> 7;
            float2 r2 = make_float2(0.0f, 0.0f);
            const float* Xq = xs + qt * 16 * H + 2 * fp;
            #pragma unroll
            for (int a = 0; a < 16; ++a) {
                float sw = sc[qt * 16 + a];
                float2 xv = *(const float2*)&Xq[a * H];
                r2.x = fmaf(sw, xv.x, r2.x);
                r2.y = fmaf(sw, xv.y, r2.y);
            }
            *(float2*)&red[tid * 2] = r2;
        }
        __syncthreads();
        if (tid < 128) {
            float2 r0 = *(const float2*)&red[tid * 2];
            float2 r1 = *(const float2*)&red[(tid + 128) * 2];
            float2 r2 = *(const float2*)&red[(tid + 256) * 2];
            float2 r3 = *(const float2*)&red[(tid + 384) * 2];
            float2 rr = make_float2(r0.x + r1.x + r2.x + r3.x,
                                    r0.y + r1.y + r2.y + r3.y);
            ((__half2*)g_h16)[(size_t)b * 128 + tid] = __floats2half2_rn(rr.x, rr.y);
        }
        __syncthreads();
    }
}

// ---------------- passes 1-2: fp16 attention ----------------
// SMEM: xsh[64][128] | qs[256] | sc[64] | red4[512] float4
#define A16_BYTES  (TILE_HB + (H + APG)*4 + 512*16 + 8)

__global__ void __launch_bounds__(512, 3) attnh_kernel(float* __restrict__ out,
                                                       int mode) {
    extern __shared__ __align__(16) unsigned char smraw[];
    __half2* xsh = (__half2*)smraw;                    // [64][128]
    float*  qs   = (float*)(smraw + TILE_HB);          // [256]
    float*  sc   = qs + H;                             // [64]
    float4* red4 = (float4*)(sc + APG);                // [512]
    uint32_t smem_base;
    asm("{ .reg .u64 t; cvta.to.shared.u64 t, %1; cvt.u32.u64 %0, t; }"
        : "=r"(smem_base) : "l"(smraw));
    uint32_t mbar = smem_base + (uint32_t)(TILE_HB + (H + APG) * 4 + 512 * 16);

    int tid  = threadIdx.x;
    int lane = tid & 31;
    int w    = tid >> 5;

    if (tid == 0)
        asm volatile("mbarrier.init.shared.b64 [%0], 1;" :: "r"(mbar) : "memory");
    __syncthreads();

    int ph = 0;
    for (int b = blockIdx.x; b < NG; b += GRIDA) {
        if (tid == 0) {
            asm volatile("mbarrier.arrive.expect_tx.shared.b64 _, [%0], %1;"
                         :: "r"(mbar), "r"(TILE_HB) : "memory");
            asm volatile("cp.async.bulk.shared::cta.global.mbarrier::complete_tx::bytes "
                         "[%0], [%1], %2, [%3];"
                         :: "r"(smem_base), "l"(g_xh2 + (size_t)b * 8192),
                            "r"(TILE_HB), "r"(mbar) : "memory");
        }

        // fused LSTM pointwise -> q (overlaps TMA)
        if (tid < H) {
            int j = tid;
            const float* gr = g_gates + (size_t)b * FOURH;
            float gi = gr[j]       + g_bc[j];
            float gf = gr[256 + j] + g_bc[256 + j];
            float gg = gr[512 + j] + g_bc[512 + j];
            float go = gr[768 + j] + g_bc[768 + j];
            float cp = (mode == 1) ? g_c0[j] : g_c[(size_t)b * H + j];
            float c  = sigmoidf_(gf) * cp + sigmoidf_(gi) * tanhf(gg);
            float q  = sigmoidf_(go) * tanhf(c);
            if (mode == 1) g_c[(size_t)b * H + j] = c;
            if (mode == 2) out[(size_t)b * (2 * H) + j] = q;
            qs[j] = q;
        }

        {
            uint32_t done;
            do {
                asm volatile(
                    "{ .reg .pred p; "
                    "mbarrier.try_wait.parity.acquire.cta.shared::cta.b64 p, [%1], %2, 0x989680; "
                    "selp.b32 %0, 1, 0, p; }"
                    : "=r"(done) : "r"(mbar), "r"(ph) : "memory");
            } while (!done);
            ph ^= 1;
        }
        __syncthreads();

        // scores: 16 warps x 4 atoms; LDS.64 x loads, float4 q loads
        float4 q4a = *(const float4*)&qs[4 * lane];
        float4 q4b = *(const float4*)&qs[128 + 4 * lane];
        #pragma unroll
        for (int aa = 0; aa < 4; ++aa) {
            int a = w * 4 + aa;
            const __half2* row = xsh + a * 128;
            uint2 ua = *(const uint2*)&row[2 * lane];        // features 4l..4l+3
            uint2 ub = *(const uint2*)&row[64 + 2 * lane];   // features 128+4l..
            float2 xa0 = __half22float2(*(__half2*)&ua.x);
            float2 xa1 = __half22float2(*(__half2*)&ua.y);
            float2 xb0 = __half22float2(*(__half2*)&ub.x);
            float2 xb1 = __half22float2(*(__half2*)&ub.y);
            float p = xa0.x*q4a.x + xa0.y*q4a.y + xa1.x*q4a.z + xa1.y*q4a.w
                    + xb0.x*q4b.x + xb0.y*q4b.y + xb1.x*q4b.z + xb1.y*q4b.w;
            #pragma unroll
            for (int off = 16; off; off >>= 1)
                p += __shfl_xor_sync(0xffffffffu, p, off);
            if (lane == 0) sc[a] = p;
        }
        __syncthreads();

        // softmax over 64 (warp 0)
        if (w == 0) {
            float v0 = sc[lane], v1 = sc[lane + 32];
            float mx = fmaxf(v0, v1);
            #pragma unroll
            for (int off = 16; off; off >>= 1)
                mx = fmaxf(mx, __shfl_xor_sync(0xffffffffu, mx, off));
            float e0 = __expf(v0 - mx), e1 = __expf(v1 - mx);
            float s = e0 + e1;
            #pragma unroll
            for (int off = 16; off; off >>= 1)
                s += __shfl_xor_sync(0xffffffffu, s, off);
            float inv = 1.0f / s;
            sc[lane]      = e0 * inv;
            sc[lane + 32] = e1 * inv;
        }
        __syncthreads();

        // weighted sum: thread -> feature quad, eighth of atoms (LDS.64 loads)
        {
            int fq = tid & 63;            // features 4fq..4fq+3
            int qt = tid >> 6;            // 0..7 (8 atoms each)
            float4 acc = make_float4(0.0f, 0.0f, 0.0f, 0.0f);
            const __half2* Xq = xsh + qt * 8 * 128 + 2 * fq;
            #pragma unroll
            for (int a = 0; a < 8; ++a) {
                float sw = sc[qt * 8 + a];
                uint2 u = *(const uint2*)&Xq[a * 128];
                float2 x0 = __half22float2(*(__half2*)&u.x);
                float2 x1 = __half22float2(*(__half2*)&u.y);
                acc.x = fmaf(sw, x0.x, acc.x);
                acc.y = fmaf(sw, x0.y, acc.y);
                acc.z = fmaf(sw, x1.x, acc.z);
                acc.w = fmaf(sw, x1.y, acc.w);
            }
            red4[tid] = acc;
        }
        __syncthreads();
        if (tid < 64) {
            float4 rr = make_float4(0.0f, 0.0f, 0.0f, 0.0f);
            #pragma unroll
            for (int g = 0; g < 8; ++g) {
                float4 v = red4[tid + 64 * g];
                rr.x += v.x; rr.y += v.y; rr.z += v.z; rr.w += v.w;
            }
            __half2 ha = __floats2half2_rn(rr.x, rr.y);
            __half2 hb = __floats2half2_rn(rr.z, rr.w);
            uint2 u;
            u.x = *(uint32_t*)&ha;
            u.y = *(uint32_t*)&hb;
            ((uint2*)g_h16)[(size_t)b * 64 + tid] = u;
            if (mode == 2)
                *(float4*)&out[(size_t)b * (2 * H) + H + 4 * tid] = rr;
        }
        __syncthreads();
    }
}

// ---------------- launch ----------------
extern "C" void kernel_launch(void* const* d_in, const int* in_sizes, int n_in,
                              void* d_out, int out_size) {
    const float* x    = (const float*)d_in[0];
    const float* W_ih = (const float*)d_in[3];
    const float* W_hh = (const float*)d_in[4];
    const float* b_ih = (const float*)d_in[5];
    const float* b_hh = (const float*)d_in[6];
    float* out = (float*)d_out;

    cudaFuncSetAttribute(attn0_kernel,
                         cudaFuncAttributeMaxDynamicSharedMemorySize, (int)A32_SMEM);
    cudaFuncSetAttribute(attnh_kernel,
                         cudaFuncAttributeMaxDynamicSharedMemorySize, (int)A16_BYTES);
    cudaFuncSetAttribute(gemm_wmma_kernel,
                         cudaFuncAttributeMaxDynamicSharedMemorySize, (int)GW_SMEM);

    prep_kernel<<<1024, 256>>>(W_ih, W_hh, b_ih, b_hh);

    dim3 ggrid(FOURH / 128, NG / 128);

    attn0_kernel<<<GRIDA, 512, A32_SMEM>>>(x);                 // step 0 + fp16 export
    gemm_wmma_kernel<<<ggrid, 256, GW_SMEM>>>();
    attnh_kernel<<<GRIDA, 512, A16_BYTES>>>(nullptr, 1);       // step 1
    gemm_wmma_kernel<<<ggrid, 256, GW_SMEM>>>();
    attnh_kernel<<<GRIDA, 512, A16_BYTES>>>(out, 2);           // step 2
}

// round 17
// speedup vs baseline: 1.4552x; 1.4552x over previous
#include <cuda_runtime.h>
#include <cuda_fp16.h>
#include <mma.h>
#include <cstdint>

using namespace nvcuda;

#define H        256
#define FOURH    1024
#define NG       2048
#define APG      64
#define GRIDA    444          // attention: 3 CTAs per SM
#define TILE_F   (APG*H)
#define TILE_B   (TILE_F*4)   // fp32 tile bytes
#define TILE_HB  (TILE_F*2)   // fp16 tile bytes

// ---------------- device scratch ----------------
__device__ __align__(128) __half g_Wc16[FOURH * H];      // fp16 folded weights
__device__ float   g_bc[FOURH];
__device__ float   g_q0[H];
__device__ float   g_c0[H];
__device__ float   g_c [NG * H];
__device__ __align__(128) __half g_h16[NG * H];          // fp16 h (= r)
__device__ float   g_gates[NG * FOURH];
__device__ __align__(128) __half2 g_xh2[(size_t)NG * 8192];  // fp16 copy of x

__device__ __forceinline__ float sigmoidf_(float v) {
    return 1.0f / (1.0f + __expf(-v));
}

// ---------------- prep ----------------
__global__ void prep_kernel(const float* __restrict__ W_ih,
                            const float* __restrict__ W_hh,
                            const float* __restrict__ b_ih,
                            const float* __restrict__ b_hh) {
    int idx = blockIdx.x * 256 + threadIdx.x;
    if (idx < FOURH * H)
        g_Wc16[idx] = __float2half(W_ih[idx] + W_hh[idx]);
    if (idx < FOURH) g_bc[idx] = b_ih[idx] + b_hh[idx];
    if (idx < H) {
        float gi = b_ih[idx]       + b_hh[idx];
        float gg = b_ih[512 + idx] + b_hh[512 + idx];
        float go = b_ih[768 + idx] + b_hh[768 + idx];
        float c  = sigmoidf_(gi) * tanhf(gg);
        g_c0[idx] = c;
        g_q0[idx] = sigmoidf_(go) * tanhf(c);
    }
}

// ---------------- GEMM: gates = h16 @ Wc16^T via wmma (fp32 accum) ----------------
#define GW_SMEM (2 * 128 * 256 * 2)

__global__ void __launch_bounds__(256) gemm_wmma_kernel() {
    extern __shared__ __align__(16) __half smh[];
    __half* As = smh;                  // [128][256]
    __half* Bs = smh + 128 * 256;      // [128][256]

    int tid = threadIdx.x;
    int mb  = blockIdx.y * 128;
    int nb  = blockIdx.x * 128;

    {
        const uint4* srcA = (const uint4*)(g_h16  + (size_t)mb * H);
        const uint4* srcB = (const uint4*)(g_Wc16 + (size_t)nb * H);
        uint4* dA = (uint4*)As;
        uint4* dB = (uint4*)Bs;
        #pragma unroll
        for (int i = 0; i < 16; ++i) dA[tid + i * 256] = srcA[tid + i * 256];
        #pragma unroll
        for (int i = 0; i < 16; ++i) dB[tid + i * 256] = srcB[tid + i * 256];
    }
    __syncthreads();

    int w  = tid >> 5;
    int wm = (w >> 1) * 32;
    int wn = (w & 1) * 64;

    wmma::fragment<wmma::accumulator, 16, 16, 16, float> acc[2][4];
    #pragma unroll
    for (int i = 0; i < 2; ++i)
        #pragma unroll
        for (int j = 0; j < 4; ++j) wmma::fill_fragment(acc[i][j], 0.0f);

    #pragma unroll
    for (int k = 0; k < H; k += 16) {
        wmma::fragment<wmma::matrix_a, 16, 16, 16, __half, wmma::row_major> af[2];
        wmma::fragment<wmma::matrix_b, 16, 16, 16, __half, wmma::col_major> bf[4];
        #pragma unroll
        for (int i = 0; i < 2; ++i)
            wmma::load_matrix_sync(af[i], As + (wm + 16 * i) * H + k, H);
        #pragma unroll
        for (int j = 0; j < 4; ++j)
            wmma::load_matrix_sync(bf[j], Bs + (wn + 16 * j) * H + k, H);
        #pragma unroll
        for (int i = 0; i < 2; ++i)
            #pragma unroll
            for (int j = 0; j < 4; ++j)
                wmma::mma_sync(acc[i][j], af[i], bf[j], acc[i][j]);
    }

    #pragma unroll
    for (int i = 0; i < 2; ++i)
        #pragma unroll
        for (int j = 0; j < 4; ++j)
            wmma::store_matrix_sync(
                &g_gates[(size_t)(mb + wm + 16 * i) * FOURH + nb + wn + 16 * j],
                acc[i][j], FOURH, wmma::mem_row_major);
}

// ---------------- pass 0 (R13-exact): fp32 attention + fp16 export ----------------
#define A32_FLOATS (TILE_F + H + APG + 512)
#define A32_SMEM   (A32_FLOATS*4 + 8)

__global__ void __launch_bounds__(512, 3) attn0_kernel(const float* __restrict__ x) {
    extern __shared__ __align__(16) unsigned char smraw[];
    float* xs  = (float*)smraw;              // [64][256] fp32
    float* qs  = xs + TILE_F;                // [256]
    float* sc  = qs + H;                     // [64]
    float* red = sc + APG;                   // [512]
    uint32_t smem_base;
    asm("{ .reg .u64 t; cvta.to.shared.u64 t, %1; cvt.u32.u64 %0, t; }"
        : "=r"(smem_base) : "l"(smraw));
    uint32_t mbar = smem_base + A32_FLOATS * 4;

    int tid  = threadIdx.x;
    int lane = tid & 31;
    int w    = tid >> 5;

    if (tid == 0)
        asm volatile("mbarrier.init.shared.b64 [%0], 1;" :: "r"(mbar) : "memory");
    __syncthreads();

    int ph = 0;
    for (int b = blockIdx.x; b < NG; b += GRIDA) {
        if (tid == 0) {
            asm volatile("mbarrier.arrive.expect_tx.shared.b64 _, [%0], %1;"
                         :: "r"(mbar), "r"(TILE_B) : "memory");
            asm volatile("cp.async.bulk.shared::cta.global.mbarrier::complete_tx::bytes "
                         "[%0], [%1], %2, [%3];"
                         :: "r"(smem_base), "l"(x + (size_t)b * TILE_F),
                            "r"(TILE_B), "r"(mbar) : "memory");
        }
        if (tid < H) qs[tid] = g_q0[tid];

        {
            uint32_t done;
            do {
                asm volatile(
                    "{ .reg .pred p; "
                    "mbarrier.try_wait.parity.acquire.cta.shared::cta.b64 p, [%1], %2, 0x989680; "
                    "selp.b32 %0, 1, 0, p; }"
                    : "=r"(done) : "r"(mbar), "r"(ph) : "memory");
            } while (!done);
            ph ^= 1;
        }
        __syncthreads();

        // export tile as fp16 (uint2 stores)
        {
            const float4* src4 = (const float4*)xs;
            uint2* dst2 = (uint2*)(g_xh2 + (size_t)b * 8192);
            #pragma unroll
            for (int it = 0; it < 8; ++it) {
                int idx = tid + it * 512;
                float4 v = src4[idx];
                __half2 h0 = __floats2half2_rn(v.x, v.y);
                __half2 h1 = __floats2half2_rn(v.z, v.w);
                uint2 u;
                u.x = *(uint32_t*)&h0;
                u.y = *(uint32_t*)&h1;
                dst2[idx] = u;
            }
        }

        // scores: 16 warps x 4 atoms (scalar conflict-free loads)
        float qreg[8];
        #pragma unroll
        for (int k = 0; k < 8; ++k) qreg[k] = qs[lane + 32 * k];
        #pragma unroll
        for (int aa = 0; aa < 4; ++aa) {
            int a = w * 4 + aa;
            const float* xr = xs + a * H;
            float p = 0.0f;
            #pragma unroll
            for (int k = 0; k < 8; ++k)
                p = fmaf(xr[lane + 32 * k], qreg[k], p);
            #pragma unroll
            for (int off = 16; off; off >>= 1)
                p += __shfl_xor_sync(0xffffffffu, p, off);
            if (lane == 0) sc[a] = p;
        }
        __syncthreads();

        // softmax over 64 (warp 0)
        if (w == 0) {
            float v0 = sc[lane], v1 = sc[lane + 32];
            float mx = fmaxf(v0, v1);
            #pragma unroll
            for (int off = 16; off; off >>= 1)
                mx = fmaxf(mx, __shfl_xor_sync(0xffffffffu, mx, off));
            float e0 = __expf(v0 - mx), e1 = __expf(v1 - mx);
            float s = e0 + e1;
            #pragma unroll
            for (int off = 16; off; off >>= 1)
                s += __shfl_xor_sync(0xffffffffu, s, off);
            float inv = 1.0f / s;
            sc[lane]      = e0 * inv;
            sc[lane + 32] = e1 * inv;
        }
        __syncthreads();

        // weighted sum (scalar conflict-free)
        {
            int j    = tid & (H - 1);
            int half = tid >> 8;
            const float* Xh = xs + half * 32 * H;
            float r = 0.0f;
            #pragma unroll
            for (int a0 = 0; a0 < 32; ++a0)
                r = fmaf(sc[half * 32 + a0], Xh[a0 * H + j], r);
            red[tid] = r;
        }
        __syncthreads();
        if (tid < H)
            g_h16[(size_t)b * H + tid] = __float2half(red[tid] + red[tid + H]);
        __syncthreads();
    }
}

// ---------------- passes 1-2: fp16 attention, 2 graphs per iteration ----------------
// SMEM: xsh[2][64][128] half2 (64KB) | qs[2][256] | sc[2][64] | red2[512] float2
#define A16_FLOATS (2*H + 2*APG + 1024)
#define A16_BYTES  (2*TILE_HB + A16_FLOATS*4 + 8)

__global__ void __launch_bounds__(512, 3) attnh_kernel(float* __restrict__ out,
                                                       int mode) {
    extern __shared__ __align__(16) unsigned char smraw[];
    __half2* xsh = (__half2*)smraw;                    // [2][64][128]
    float* qs  = (float*)(smraw + 2 * TILE_HB);        // [2][256]
    float* sc  = qs + 2 * H;                           // [2][64]
    float* red = sc + 2 * APG;                         // [512] float2
    uint32_t smem_base;
    asm("{ .reg .u64 t; cvta.to.shared.u64 t, %1; cvt.u32.u64 %0, t; }"
        : "=r"(smem_base) : "l"(smraw));
    uint32_t mbar = smem_base + (uint32_t)(2 * TILE_HB + A16_FLOATS * 4);

    int tid  = threadIdx.x;
    int lane = tid & 31;
    int w    = tid >> 5;
    int bid  = blockIdx.x;
    int G    = (NG - bid + GRIDA - 1) / GRIDA;

    if (tid == 0)
        asm volatile("mbarrier.init.shared.b64 [%0], 1;" :: "r"(mbar) : "memory");
    __syncthreads();

    int ph = 0;
    for (int k = 0; k < G; k += 2) {
        int b1   = bid + GRIDA * k;
        int has2 = (k + 1 < G);
        int b2   = b1 + GRIDA;

        if (tid == 0) {
            uint32_t bytes = has2 ? 2 * TILE_HB : TILE_HB;
            asm volatile("mbarrier.arrive.expect_tx.shared.b64 _, [%0], %1;"
                         :: "r"(mbar), "r"(bytes) : "memory");
            asm volatile("cp.async.bulk.shared::cta.global.mbarrier::complete_tx::bytes "
                         "[%0], [%1], %2, [%3];"
                         :: "r"(smem_base), "l"(g_xh2 + (size_t)b1 * 8192),
                            "r"(TILE_HB), "r"(mbar) : "memory");
            if (has2)
                asm volatile("cp.async.bulk.shared::cta.global.mbarrier::complete_tx::bytes "
                             "[%0], [%1], %2, [%3];"
                             :: "r"(smem_base + TILE_HB), "l"(g_xh2 + (size_t)b2 * 8192),
                                "r"(TILE_HB), "r"(mbar) : "memory");
        }

        // fused LSTM pointwise for both graphs (overlaps TMA)
        {
            int g = tid >> 8;          // 0 or 1
            int j = tid & 255;
            int bg = g ? b2 : b1;
            if (g == 0 || has2) {
                const float* gr = g_gates + (size_t)bg * FOURH;
                float gi = gr[j]       + g_bc[j];
                float gf = gr[256 + j] + g_bc[256 + j];
                float gg = gr[512 + j] + g_bc[512 + j];
                float go = gr[768 + j] + g_bc[768 + j];
                float cp = (mode == 1) ? g_c0[j] : g_c[(size_t)bg * H + j];
                float c  = sigmoidf_(gf) * cp + sigmoidf_(gi) * tanhf(gg);
                float q  = sigmoidf_(go) * tanhf(c);
                if (mode == 1) g_c[(size_t)bg * H + j] = c;
                if (mode == 2) out[(size_t)bg * (2 * H) + j] = q;
                qs[g * H + j] = q;
            }
        }

        {
            uint32_t done;
            do {
                asm volatile(
                    "{ .reg .pred p; "
                    "mbarrier.try_wait.parity.acquire.cta.shared::cta.b64 p, [%1], %2, 0x989680; "
                    "selp.b32 %0, 1, 0, p; }"
                    : "=r"(done) : "r"(mbar), "r"(ph) : "memory");
            } while (!done);
            ph ^= 1;
        }
        __syncthreads();

        // scores: warps 0-7 -> graph A (8 atoms each), warps 8-15 -> graph B
        {
            int g = w >> 3;
            if (g == 0 || has2) {
                const float* qg = qs + g * H;
                float q0 = qg[2 * lane], q1 = qg[2 * lane + 1];
                float q2 = qg[64 + 2 * lane], q3 = qg[64 + 2 * lane + 1];
                float q4 = qg[128 + 2 * lane], q5 = qg[128 + 2 * lane + 1];
                float q6 = qg[192 + 2 * lane], q7 = qg[192 + 2 * lane + 1];
                #pragma unroll
                for (int aa = 0; aa < 8; ++aa) {
                    int a = (w & 7) * 8 + aa;
                    const __half2* row = xsh + (g * 64 + a) * 128;
                    float2 x0 = __half22float2(row[lane]);
                    float2 x1 = __half22float2(row[32 + lane]);
                    float2 x2 = __half22float2(row[64 + lane]);
                    float2 x3 = __half22float2(row[96 + lane]);
                    float p = x0.x*q0 + x0.y*q1 + x1.x*q2 + x1.y*q3
                            + x2.x*q4 + x2.y*q5 + x3.x*q6 + x3.y*q7;
                    #pragma unroll
                    for (int off = 16; off; off >>= 1)
                        p += __shfl_xor_sync(0xffffffffu, p, off);
                    if (lane == 0) sc[g * APG + a] = p;
                }
            }
        }
        __syncthreads();

        // softmax: warp 0 -> graph A, warp 1 -> graph B (parallel)
        if (w < 2 && (w == 0 || has2)) {
            float* sg = sc + w * APG;
            float v0 = sg[lane], v1 = sg[lane + 32];
            float mx = fmaxf(v0, v1);
            #pragma unroll
            for (int off = 16; off; off >>= 1)
                mx = fmaxf(mx, __shfl_xor_sync(0xffffffffu, mx, off));
            float e0 = __expf(v0 - mx), e1 = __expf(v1 - mx);
            float s = e0 + e1;
            #pragma unroll
            for (int off = 16; off; off >>= 1)
                s += __shfl_xor_sync(0xffffffffu, s, off);
            float inv = 1.0f / s;
            sg[lane]      = e0 * inv;
            sg[lane + 32] = e1 * inv;
        }
        __syncthreads();

        // weighted sum: thread -> (graph, feature pair, half of atoms)
        {
            int g  = tid >> 8;           // 0/1
            int fp = tid & 127;          // feature pair
            int qt = (tid >> 7) & 1;     // atom half (32 atoms)
            if (g == 0 || has2) {
                float2 r2 = make_float2(0.0f, 0.0f);
                const __half2* Xq = xsh + (g * 64 + qt * 32) * 128 + fp;
                const float* sg = sc + g * APG + qt * 32;
                #pragma unroll
                for (int a = 0; a < 32; ++a) {
                    float sw = sg[a];
                    float2 xv = __half22float2(Xq[a * 128]);
                    r2.x = fmaf(sw, xv.x, r2.x);
                    r2.y = fmaf(sw, xv.y, r2.y);
                }
                *(float2*)&red[tid * 2] = r2;
            }
        }
        __syncthreads();
        if (tid < 256) {
            int g  = tid >> 7;           // 0/1
            int fp = tid & 127;
            if (g == 0 || has2) {
                int bg = g ? b2 : b1;
                float2 r0 = *(const float2*)&red[(g * 256 + fp) * 2];
                float2 r1 = *(const float2*)&red[(g * 256 + 128 + fp) * 2];
                float2 rr = make_float2(r0.x + r1.x, r0.y + r1.y);
                ((__half2*)g_h16)[(size_t)bg * 128 + fp] = __floats2half2_rn(rr.x, rr.y);
                if (mode == 2)
                    *(float2*)&out[(size_t)bg * (2 * H) + H + 2 * fp] = rr;
            }
        }
        __syncthreads();
    }
}

// ---------------- launch ----------------
extern "C" void kernel_launch(void* const* d_in, const int* in_sizes, int n_in,
                              void* d_out, int out_size) {
    const float* x    = (const float*)d_in[0];
    const float* W_ih = (const float*)d_in[3];
    const float* W_hh = (const float*)d_in[4];
    const float* b_ih = (const float*)d_in[5];
    const float* b_hh = (const float*)d_in[6];
    float* out = (float*)d_out;

    cudaFuncSetAttribute(attn0_kernel,
                         cudaFuncAttributeMaxDynamicSharedMemorySize, (int)A32_SMEM);
    cudaFuncSetAttribute(attnh_kernel,
                         cudaFuncAttributeMaxDynamicSharedMemorySize, (int)A16_BYTES);
    cudaFuncSetAttribute(gemm_wmma_kernel,
                         cudaFuncAttributeMaxDynamicSharedMemorySize, (int)GW_SMEM);

    prep_kernel<<<1024, 256>>>(W_ih, W_hh, b_ih, b_hh);

    dim3 ggrid(FOURH / 128, NG / 128);

    attn0_kernel<<<GRIDA, 512, A32_SMEM>>>(x);                 // step 0 + fp16 export
    gemm_wmma_kernel<<<ggrid, 256, GW_SMEM>>>();
    attnh_kernel<<<GRIDA, 512, A16_BYTES>>>(nullptr, 1);       // step 1
    gemm_wmma_kernel<<<ggrid, 256, GW_SMEM>>>();
    attnh_kernel<<<GRIDA, 512, A16_BYTES>>>(out, 2);           // step 2
}